// round 13
// baseline (speedup 1.0000x reference)
#include <cuda_runtime.h>
#include <cuda_pipeline.h>
#include <mma.h>

using namespace nvcuda;

#define NTOK 65536          // B * H * W = 16 * 64 * 64
#define EDIM 512
#define EHID 2048
#define TD (NTOK * EDIM)    // elements per (token, dim) tensor

// ---------------- scratch (static device globals; no allocations) ----------------
__device__ float g_xw[TD];
__device__ float g_sw[TD];
__device__ float g_hw[TD];
__device__ float g_q[TD];
__device__ float g_k[TD];
__device__ float g_v[TD];
__device__ float g_vs[TD];
__device__ float g_vh[TD];
__device__ float g_o[TD];
__device__ float g_os[TD];
__device__ float g_oh[TD];
__device__ float g_hid[NTOK * EHID];

// windowed token t -> original token (also the window-reverse scatter target)
__device__ __forceinline__ int winrev_row(int t) {
    int b   = t >> 12;          // 4096 tokens per image
    int win = (t >> 6) & 63;    // wh*8 + ww
    int n   = t & 63;           // nh*8 + nw
    int oh  = (((win >> 3) << 3) + (n >> 3) + 4) & 63;
    int ow  = (((win & 7) << 3) + (n & 7) + 4) & 63;
    return (b << 12) + (oh << 6) + ow;
}

// ---------------- gather: cyclic shift (-4,-4) + window partition ----------------
__global__ __launch_bounds__(128) void gather3(
    const float* __restrict__ x, const float* __restrict__ s, const float* __restrict__ h,
    float* __restrict__ xw, float* __restrict__ sw, float* __restrict__ hw)
{
    int t = blockIdx.x;
    int c = threadIdx.x << 2;
    size_t src = (size_t)winrev_row(t) * EDIM + c;
    size_t dst = (size_t)t * EDIM + c;
    *(float4*)(xw + dst) = *(const float4*)(x + src);
    *(float4*)(sw + dst) = *(const float4*)(s + src);
    *(float4*)(hw + dst) = *(const float4*)(h + src);
}

// ---------------- tf32 wmma GEMM v5: 128x128 tile, 4-stage cp.async, 1 sync/tile ----
// A: M x K row-major, B: K x N row-major. fp32 operands; HMMA truncates to tf32 (RZ).
// 8 warps, 32x64 warp tile (acc 2x4). regs capped at 128 -> 2 CTAs/SM.
// 4 stages: prefetch at iter kt targets stage (kt+3)&3 = (kt-1)&3, whose readers
// all passed this iteration's single __syncthreads -> no trailing barrier needed.
// mode 0: C = alpha * val
// mode 1: C = relu(val)
// mode 2: C += val                (in-place residual accumulate)
// mode 3: C[map(row)] = res[map(row)] + val   (window-reverse scatter + residual)
#define BM 128
#define BN 128
#define BK 16
#define A_PAD 20                        // 128x16 tile at stride 20 (conflict-free)
#define B_PAD 132                       // 16x128 tile at stride 132
#define A_STAGE (BM * A_PAD)            // 2560 floats
#define B_STAGE (BK * B_PAD)            // 2112 floats
#define NSTAGE 4
#define GEMM_SMEM (NSTAGE * (A_STAGE + B_STAGE) * 4)   // 74,752 bytes

__global__ __launch_bounds__(256, 2) void gemm_tf32_v5(
    const float* __restrict__ A, const float* __restrict__ Bm,
    const float* __restrict__ bias, float* __restrict__ C,
    const float* __restrict__ res,
    int M, int N, int K, int mode, float alpha)
{
    extern __shared__ float sm[];
    float* As = sm;                       // 4 stages of 128x20
    float* Bs = sm + NSTAGE * A_STAGE;    // 4 stages of 16x132

    int tid = threadIdx.x;
    int warp = tid >> 5;
    int wm = warp >> 1;                   // 0..3: 32-row band
    int wn = warp & 1;                    // 0..1: 64-col band
    int m0 = blockIdx.y * BM;
    int n0 = blockIdx.x * BN;

    wmma::fragment<wmma::accumulator, 16, 16, 8, float> acc[2][4];
    #pragma unroll
    for (int i = 0; i < 2; i++)
        #pragma unroll
        for (int j = 0; j < 4; j++) wmma::fill_fragment(acc[i][j], 0.0f);

    // fixed per-thread load coords
    int a_r0 = (tid * 2) >> 2,     a_c0 = ((tid * 2) & 3) << 2;
    int a_r1 = (tid * 2 + 1) >> 2, a_c1 = ((tid * 2 + 1) & 3) << 2;
    int b_r0 = (tid * 2) >> 5,     b_c0 = ((tid * 2) & 31) << 2;
    int b_r1 = (tid * 2 + 1) >> 5, b_c1 = ((tid * 2 + 1) & 31) << 2;

    auto load_tile = [&](int s, int ko) {
        float* as = As + s * A_STAGE;
        float* bs = Bs + s * B_STAGE;
        __pipeline_memcpy_async(as + a_r0 * A_PAD + a_c0,
                                A + (size_t)(m0 + a_r0) * K + ko + a_c0, 16);
        __pipeline_memcpy_async(as + a_r1 * A_PAD + a_c1,
                                A + (size_t)(m0 + a_r1) * K + ko + a_c1, 16);
        __pipeline_memcpy_async(bs + b_r0 * B_PAD + b_c0,
                                Bm + (size_t)(ko + b_r0) * N + n0 + b_c0, 16);
        __pipeline_memcpy_async(bs + b_r1 * B_PAD + b_c1,
                                Bm + (size_t)(ko + b_r1) * N + n0 + b_c1, 16);
    };

    int ktiles = K / BK;                  // >= 32 for all our shapes
    int last = ktiles - 1;
    load_tile(0, 0);         __pipeline_commit();
    load_tile(1, BK);        __pipeline_commit();
    load_tile(2, 2 * BK);    __pipeline_commit();

    for (int kt = 0; kt < ktiles; kt++) {
        // wait until group kt is complete (constant-immediate variants)
        if (kt + 2 <= last)      __pipeline_wait_prior(2);
        else if (kt + 1 <= last) __pipeline_wait_prior(1);
        else                     __pipeline_wait_prior(0);
        __syncthreads();

        // prefetch stage (kt+3)&3 == (kt-1)&3: its readers passed the sync above
        if (kt + 3 <= last) {
            load_tile((kt + 3) & 3, (kt + 3) * BK);
            __pipeline_commit();
        }

        float* as = As + (kt & 3) * A_STAGE;
        float* bs = Bs + (kt & 3) * B_STAGE;
        #pragma unroll
        for (int ks = 0; ks < BK; ks += 8) {
            wmma::fragment<wmma::matrix_a, 16, 16, 8, wmma::precision::tf32, wmma::row_major> af[2];
            wmma::fragment<wmma::matrix_b, 16, 16, 8, wmma::precision::tf32, wmma::row_major> bf[4];
            #pragma unroll
            for (int i = 0; i < 2; i++)
                wmma::load_matrix_sync(af[i], as + (wm * 32 + i * 16) * A_PAD + ks, A_PAD);
            #pragma unroll
            for (int j = 0; j < 4; j++)
                wmma::load_matrix_sync(bf[j], bs + ks * B_PAD + wn * 64 + j * 16, B_PAD);
            #pragma unroll
            for (int i = 0; i < 2; i++)
                #pragma unroll
                for (int j = 0; j < 4; j++)
                    wmma::mma_sync(acc[i][j], af[i], bf[j], acc[i][j]);
        }
    }
    __syncthreads();                      // all k-loop reads done before smem reuse

    // epilogue in two 64x128 halves staged at stride 132
    #pragma unroll 1
    for (int half = 0; half < 2; half++) {
        if ((wm >> 1) == half) {
            int rbase = wm * 32 - half * 64;
            #pragma unroll
            for (int i = 0; i < 2; i++)
                #pragma unroll
                for (int j = 0; j < 4; j++)
                    wmma::store_matrix_sync(sm + (rbase + i * 16) * B_PAD + wn * 64 + j * 16,
                                            acc[i][j], B_PAD, wmma::mem_row_major);
        }
        __syncthreads();
        // 64*128/4 = 2048 float4, 8 per thread
        for (int e = tid; e < 2048; e += 256) {
            int r = e >> 5;
            int c = (e & 31) << 2;
            float4 val = *(float4*)(sm + r * B_PAD + c);
            int gn = n0 + c;
            float4 bb = *(const float4*)(bias + gn);
            val.x += bb.x; val.y += bb.y; val.z += bb.z; val.w += bb.w;
            int gm = m0 + half * 64 + r;
            if (mode == 0) {
                val.x *= alpha; val.y *= alpha; val.z *= alpha; val.w *= alpha;
                *(float4*)(C + (size_t)gm * N + gn) = val;
            } else if (mode == 1) {
                val.x = fmaxf(val.x, 0.f); val.y = fmaxf(val.y, 0.f);
                val.z = fmaxf(val.z, 0.f); val.w = fmaxf(val.w, 0.f);
                *(float4*)(C + (size_t)gm * N + gn) = val;
            } else if (mode == 2) {
                float4 cv = *(float4*)(C + (size_t)gm * N + gn);
                val.x += cv.x; val.y += cv.y; val.z += cv.z; val.w += cv.w;
                *(float4*)(C + (size_t)gm * N + gn) = val;
            } else {
                size_t off = (size_t)winrev_row(gm) * N + gn;
                float4 rv = *(const float4*)(res + off);
                val.x += rv.x; val.y += rv.y; val.z += rv.z; val.w += rv.w;
                *(float4*)(C + off) = val;
            }
        }
        __syncthreads();
    }
}

// ---------------- attention: one block per (window, head) ----------------
// dynamic smem (49,664 B): qs 64x64 (reused for V), ktr stride-65, ps stride-65
#define PS_STRIDE 65
__global__ __launch_bounds__(256) void attn_kernel(
    const float* __restrict__ q, const float* __restrict__ k,
    const float* __restrict__ v, const float* __restrict__ vs, const float* __restrict__ vh,
    const float* __restrict__ rpb,
    float* __restrict__ o, float* __restrict__ os, float* __restrict__ oh)
{
    extern __shared__ float dsm[];
    float* qs  = dsm;                 // 64*64 = 4096
    float* ktr = dsm + 4096;          // 64*65 = 4160, kt[d*65 + m]
    float* ps  = dsm + 4096 + 4160;   // 64*65 = 4160, ps[n*65 + m]

    int win = blockIdx.x;
    int head = blockIdx.y;
    int tid = threadIdx.x;
    size_t base = (size_t)win * 64 * EDIM + head * 64;

    for (int f4 = tid; f4 < 1024; f4 += 256) {
        int n = f4 >> 4;
        int c = (f4 & 15) << 2;
        float4 qv = *(const float4*)(q + base + (size_t)n * EDIM + c);
        *(float4*)(qs + n * 64 + c) = qv;
        float4 kv = *(const float4*)(k + base + (size_t)n * EDIM + c);
        ktr[(c + 0) * 65 + n] = kv.x;
        ktr[(c + 1) * 65 + n] = kv.y;
        ktr[(c + 2) * 65 + n] = kv.z;
        ktr[(c + 3) * 65 + n] = kv.w;
    }
    __syncthreads();

    int n0 = (tid >> 4) << 2;
    int m0 = (tid & 15) << 2;

    float acc[4][4];
    #pragma unroll
    for (int i = 0; i < 4; i++)
        #pragma unroll
        for (int j = 0; j < 4; j++) acc[i][j] = 0.f;

    #pragma unroll 4
    for (int d = 0; d < 64; d++) {
        float qr[4], kr[4];
        #pragma unroll
        for (int i = 0; i < 4; i++) qr[i] = qs[(n0 + i) * 64 + d];
        #pragma unroll
        for (int j = 0; j < 4; j++) kr[j] = ktr[d * 65 + m0 + j];
        #pragma unroll
        for (int i = 0; i < 4; i++)
            #pragma unroll
            for (int j = 0; j < 4; j++)
                acc[i][j] = fmaf(qr[i], kr[j], acc[i][j]);
    }

    // rel-pos bias + shifted-window mask (window coordinates, unrolled mask grid)
    int wi = win & 63;
    int wh = wi >> 3, ww = wi & 7;
    #pragma unroll
    for (int i = 0; i < 4; i++) {
        int nn = n0 + i;
        int ni = nn >> 3, nj = nn & 7;
        int yn = wh * 8 + ni, xn = ww * 8 + nj;
        int idn = ((yn < 56) ? 0 : (yn < 60) ? 1 : 2) * 3 +
                  ((xn < 56) ? 0 : (xn < 60) ? 1 : 2);
        #pragma unroll
        for (int j = 0; j < 4; j++) {
            int mm = m0 + j;
            int mi = mm >> 3, mj = mm & 7;
            float rb = rpb[(((ni - mi + 7) * 15) + (nj - mj + 7)) * 8 + head];
            int ym = wh * 8 + mi, xm = ww * 8 + mj;
            int idm = ((ym < 56) ? 0 : (ym < 60) ? 1 : 2) * 3 +
                      ((xm < 56) ? 0 : (xm < 60) ? 1 : 2);
            float msk = (idn == idm) ? 0.f : -100.f;
            ps[nn * PS_STRIDE + mm] = acc[i][j] + rb + msk;
        }
    }
    __syncthreads();

    // softmax: one thread per row (stride-65 -> conflict-free)
    if (tid < 64) {
        float mx = -1e30f;
        for (int m = 0; m < 64; m++) mx = fmaxf(mx, ps[tid * PS_STRIDE + m]);
        float sum = 0.f;
        for (int m = 0; m < 64; m++) {
            float e = __expf(ps[tid * PS_STRIDE + m] - mx);
            ps[tid * PS_STRIDE + m] = e;
            sum += e;
        }
        float inv = 1.f / sum;
        for (int m = 0; m < 64; m++) ps[tid * PS_STRIDE + m] *= inv;
    }

    const float* vptr[3] = {v, vs, vh};
    float* optr[3] = {o, os, oh};
    #pragma unroll 1
    for (int t3 = 0; t3 < 3; t3++) {
        __syncthreads();                                  // qs free to reuse
        const float* vp = vptr[t3];
        for (int f4 = tid; f4 < 1024; f4 += 256) {
            int n = f4 >> 4;
            int c = (f4 & 15) << 2;
            *(float4*)(qs + n * 64 + c) = *(const float4*)(vp + base + (size_t)n * EDIM + c);
        }
        __syncthreads();
        float oa[4][4];
        #pragma unroll
        for (int i = 0; i < 4; i++)
            #pragma unroll
            for (int j = 0; j < 4; j++) oa[i][j] = 0.f;
        #pragma unroll 4
        for (int m = 0; m < 64; m++) {
            float pr[4];
            #pragma unroll
            for (int i = 0; i < 4; i++) pr[i] = ps[(n0 + i) * PS_STRIDE + m];
            float4 vv = *(const float4*)(qs + m * 64 + m0);
            #pragma unroll
            for (int i = 0; i < 4; i++) {
                oa[i][0] = fmaf(pr[i], vv.x, oa[i][0]);
                oa[i][1] = fmaf(pr[i], vv.y, oa[i][1]);
                oa[i][2] = fmaf(pr[i], vv.z, oa[i][2]);
                oa[i][3] = fmaf(pr[i], vv.w, oa[i][3]);
            }
        }
        float* op = optr[t3];
        #pragma unroll
        for (int i = 0; i < 4; i++) {
            float4 w4 = make_float4(oa[i][0], oa[i][1], oa[i][2], oa[i][3]);
            *(float4*)(op + base + (size_t)(n0 + i) * EDIM + m0) = w4;
        }
    }
}

#define ATTN_SMEM ((4096 + 4160 + 4160) * 4)

// ---------------- host launcher ----------------
extern "C" void kernel_launch(void* const* d_in, const int* in_sizes, int n_in,
                              void* d_out, int out_size)
{
    (void)in_sizes; (void)n_in; (void)out_size;

    const float* x    = (const float*)d_in[0];
    const float* scl  = (const float*)d_in[1];
    const float* sft  = (const float*)d_in[2];
    const float* wq   = (const float*)d_in[3];
    const float* bq   = (const float*)d_in[4];
    const float* wk   = (const float*)d_in[5];
    const float* bk   = (const float*)d_in[6];
    const float* wv   = (const float*)d_in[7];
    const float* bv   = (const float*)d_in[8];
    const float* wvs  = (const float*)d_in[9];
    const float* bvs  = (const float*)d_in[10];
    const float* wvh  = (const float*)d_in[11];
    const float* bvh  = (const float*)d_in[12];
    const float* wpx  = (const float*)d_in[13];
    const float* bpx  = (const float*)d_in[14];
    const float* wps  = (const float*)d_in[15];
    const float* bps  = (const float*)d_in[16];
    const float* wph  = (const float*)d_in[17];
    const float* bph  = (const float*)d_in[18];
    const float* rpb  = (const float*)d_in[19];
    const float* w1x  = (const float*)d_in[20];
    const float* b1x  = (const float*)d_in[21];
    const float* w2x  = (const float*)d_in[22];
    const float* b2x  = (const float*)d_in[23];
    const float* w1s  = (const float*)d_in[24];
    const float* b1s  = (const float*)d_in[25];
    const float* w2s  = (const float*)d_in[26];
    const float* b2s  = (const float*)d_in[27];
    const float* w1h  = (const float*)d_in[28];
    const float* b1h  = (const float*)d_in[29];
    const float* w2h  = (const float*)d_in[30];
    const float* b2h  = (const float*)d_in[31];

    float *p_xw, *p_sw, *p_hw, *p_q, *p_k, *p_v, *p_vs, *p_vh, *p_o, *p_os, *p_oh, *p_hid;
    cudaGetSymbolAddress((void**)&p_xw, g_xw);
    cudaGetSymbolAddress((void**)&p_sw, g_sw);
    cudaGetSymbolAddress((void**)&p_hw, g_hw);
    cudaGetSymbolAddress((void**)&p_q,  g_q);
    cudaGetSymbolAddress((void**)&p_k,  g_k);
    cudaGetSymbolAddress((void**)&p_v,  g_v);
    cudaGetSymbolAddress((void**)&p_vs, g_vs);
    cudaGetSymbolAddress((void**)&p_vh, g_vh);
    cudaGetSymbolAddress((void**)&p_o,  g_o);
    cudaGetSymbolAddress((void**)&p_os, g_os);
    cudaGetSymbolAddress((void**)&p_oh, g_oh);
    cudaGetSymbolAddress((void**)&p_hid, g_hid);

    float* outx = (float*)d_out;
    float* outs = outx + (size_t)TD;
    float* outh = outx + (size_t)2 * TD;

    cudaFuncSetAttribute(attn_kernel, cudaFuncAttributeMaxDynamicSharedMemorySize, ATTN_SMEM);
    cudaFuncSetAttribute(gemm_tf32_v5, cudaFuncAttributeMaxDynamicSharedMemorySize, GEMM_SMEM);

    dim3 blk(256);
    dim3 g512(EDIM / BN, NTOK / BM);    // (4, 512)
    dim3 g2048(EHID / BN, NTOK / BM);   // (16, 512)

    // 1. shift + window partition for x / scale / shift
    gather3<<<NTOK, 128>>>(x, scl, sft, p_xw, p_sw, p_hw);

    // 2. projections (q scaled by HD^-0.5 = 0.125)
    gemm_tf32_v5<<<g512, blk, GEMM_SMEM>>>(p_xw, wq,  bq,  p_q,  nullptr, NTOK, EDIM, EDIM, 0, 0.125f);
    gemm_tf32_v5<<<g512, blk, GEMM_SMEM>>>(p_xw, wk,  bk,  p_k,  nullptr, NTOK, EDIM, EDIM, 0, 1.f);
    gemm_tf32_v5<<<g512, blk, GEMM_SMEM>>>(p_xw, wv,  bv,  p_v,  nullptr, NTOK, EDIM, EDIM, 0, 1.f);
    gemm_tf32_v5<<<g512, blk, GEMM_SMEM>>>(p_sw, wvs, bvs, p_vs, nullptr, NTOK, EDIM, EDIM, 0, 1.f);
    gemm_tf32_v5<<<g512, blk, GEMM_SMEM>>>(p_hw, wvh, bvh, p_vh, nullptr, NTOK, EDIM, EDIM, 0, 1.f);

    // 3. windowed attention (shared softmax, three V streams)
    attn_kernel<<<dim3(1024, 8), 256, ATTN_SMEM>>>(p_q, p_k, p_v, p_vs, p_vh, rpb, p_o, p_os, p_oh);

    // 4. output projections + window reverse + residual (scatter into d_out)
    gemm_tf32_v5<<<g512, blk, GEMM_SMEM>>>(p_o,  wpx, bpx, outx, x,   NTOK, EDIM, EDIM, 3, 1.f);
    gemm_tf32_v5<<<g512, blk, GEMM_SMEM>>>(p_os, wps, bps, outs, scl, NTOK, EDIM, EDIM, 3, 1.f);
    gemm_tf32_v5<<<g512, blk, GEMM_SMEM>>>(p_oh, wph, bph, outh, sft, NTOK, EDIM, EDIM, 3, 1.f);

    // 5. MLPs with residual accumulate
    gemm_tf32_v5<<<g2048, blk, GEMM_SMEM>>>(outx,  w1x, b1x, p_hid, nullptr, NTOK, EHID, EDIM, 1, 1.f);
    gemm_tf32_v5<<<g512,  blk, GEMM_SMEM>>>(p_hid, w2x, b2x, outx,  nullptr, NTOK, EDIM, EHID, 2, 1.f);

    gemm_tf32_v5<<<g2048, blk, GEMM_SMEM>>>(outs,  w1s, b1s, p_hid, nullptr, NTOK, EHID, EDIM, 1, 1.f);
    gemm_tf32_v5<<<g512,  blk, GEMM_SMEM>>>(p_hid, w2s, b2s, outs,  nullptr, NTOK, EDIM, EHID, 2, 1.f);

    gemm_tf32_v5<<<g2048, blk, GEMM_SMEM>>>(outh,  w1h, b1h, p_hid, nullptr, NTOK, EHID, EDIM, 1, 1.f);
    gemm_tf32_v5<<<g512,  blk, GEMM_SMEM>>>(p_hid, w2h, b2h, outh,  nullptr, NTOK, EDIM, EHID, 2, 1.f);
}

// round 15
// speedup vs baseline: 1.6843x; 1.6843x over previous
#include <cuda_runtime.h>
#include <cuda_pipeline.h>
#include <mma.h>

using namespace nvcuda;

#define NTOK 65536          // B * H * W = 16 * 64 * 64
#define EDIM 512
#define EHID 2048
#define TD (NTOK * EDIM)    // elements per (token, dim) tensor

// ---------------- scratch (static device globals; no allocations) ----------------
__device__ float g_xw[TD];
__device__ float g_sw[TD];
__device__ float g_hw[TD];
__device__ float g_q[TD];
__device__ float g_k[TD];
__device__ float g_v[TD];
__device__ float g_vs[TD];
__device__ float g_vh[TD];
__device__ float g_o[TD];
__device__ float g_os[TD];
__device__ float g_oh[TD];
__device__ float g_hid[NTOK * EHID];

// windowed token t -> original token (also the window-reverse scatter target)
__device__ __forceinline__ int winrev_row(int t) {
    int b   = t >> 12;          // 4096 tokens per image
    int win = (t >> 6) & 63;    // wh*8 + ww
    int n   = t & 63;           // nh*8 + nw
    int oh  = (((win >> 3) << 3) + (n >> 3) + 4) & 63;
    int ow  = (((win & 7) << 3) + (n & 7) + 4) & 63;
    return (b << 12) + (oh << 6) + ow;
}

// ---------------- gather: cyclic shift (-4,-4) + window partition ----------------
__global__ __launch_bounds__(128) void gather3(
    const float* __restrict__ x, const float* __restrict__ s, const float* __restrict__ h,
    float* __restrict__ xw, float* __restrict__ sw, float* __restrict__ hw)
{
    int t = blockIdx.x;
    int c = threadIdx.x << 2;
    size_t src = (size_t)winrev_row(t) * EDIM + c;
    size_t dst = (size_t)t * EDIM + c;
    *(float4*)(xw + dst) = *(const float4*)(x + src);
    *(float4*)(sw + dst) = *(const float4*)(s + src);
    *(float4*)(hw + dst) = *(const float4*)(h + src);
}

// ---------------- tf32 wmma GEMM v6: 128x128 tile, BK=32, 2-stage, 1 sync/tile ----
// A: M x K row-major, B: K x N row-major. fp32 operands; HMMA truncates to tf32 (RZ).
// 8 warps, 32x64 warp tile (acc 2x4). regs capped at 128 -> 2 CTAs/SM.
// Race-free single-sync 2-stage loop: wait + barrier BEFORE issuing the next
// prefetch, so the stage being overwritten has no outstanding readers, and only
// ONE tile-group is in flight during compute (shallow queue; avoids the L1tex
// contention that sank the 4-stage variant).
// mode 0: C = alpha * val
// mode 1: C = relu(val)
// mode 2: C += val                (in-place residual accumulate)
// mode 3: C[map(row)] = res[map(row)] + val   (window-reverse scatter + residual)
#define BM 128
#define BN 128
#define BK 32
#define A_PAD 36                        // 128x32 tile at stride 36 (2-way worst case)
#define B_PAD 132                       // 32x128 tile at stride 132
#define A_STAGE (BM * A_PAD)            // 4608 floats
#define B_STAGE (BK * B_PAD)            // 4224 floats
#define GEMM_SMEM ((2 * A_STAGE + 2 * B_STAGE) * 4)   // 70,656 bytes

__global__ __launch_bounds__(256, 2) void gemm_tf32_v6(
    const float* __restrict__ A, const float* __restrict__ Bm,
    const float* __restrict__ bias, float* __restrict__ C,
    const float* __restrict__ res,
    int M, int N, int K, int mode, float alpha)
{
    extern __shared__ float sm[];
    float* As = sm;                     // 2 stages of 128x36
    float* Bs = sm + 2 * A_STAGE;       // 2 stages of 32x132

    int tid = threadIdx.x;
    int warp = tid >> 5;
    int wm = warp >> 1;                 // 0..3: 32-row band
    int wn = warp & 1;                  // 0..1: 64-col band
    int m0 = blockIdx.y * BM;
    int n0 = blockIdx.x * BN;

    wmma::fragment<wmma::accumulator, 16, 16, 8, float> acc[2][4];
    #pragma unroll
    for (int i = 0; i < 2; i++)
        #pragma unroll
        for (int j = 0; j < 4; j++) wmma::fill_fragment(acc[i][j], 0.0f);

    // tile loader: A 1024 float4 (4/thread), B 1024 float4 (4/thread)
    auto load_tile = [&](int s, int ko) {
        float* as = As + s * A_STAGE;
        float* bs = Bs + s * B_STAGE;
        #pragma unroll
        for (int i = 0; i < 4; i++) {
            int id = tid + 256 * i;
            int r = id >> 3, c = (id & 7) << 2;         // 8 float4 per 32-col row
            __pipeline_memcpy_async(as + r * A_PAD + c,
                                    A + (size_t)(m0 + r) * K + ko + c, 16);
        }
        #pragma unroll
        for (int i = 0; i < 4; i++) {
            int id = tid + 256 * i;
            int r = id >> 5, c = (id & 31) << 2;        // 32 float4 per 128-col row
            __pipeline_memcpy_async(bs + r * B_PAD + c,
                                    Bm + (size_t)(ko + r) * N + n0 + c, 16);
        }
    };

    int ktiles = K / BK;                // 16 (K=512) or 64 (K=2048)
    load_tile(0, 0);
    __pipeline_commit();

    for (int kt = 0; kt < ktiles; kt++) {
        __pipeline_wait_prior(0);       // stage kt&1 data landed
        __syncthreads();                // ...and visible; other stage has no readers
        if (kt + 1 < ktiles) {
            load_tile((kt + 1) & 1, (kt + 1) * BK);
            __pipeline_commit();
        }

        float* as = As + (kt & 1) * A_STAGE;
        float* bs = Bs + (kt & 1) * B_STAGE;
        #pragma unroll
        for (int ks = 0; ks < BK; ks += 8) {
            wmma::fragment<wmma::matrix_a, 16, 16, 8, wmma::precision::tf32, wmma::row_major> af[2];
            wmma::fragment<wmma::matrix_b, 16, 16, 8, wmma::precision::tf32, wmma::row_major> bf[4];
            #pragma unroll
            for (int i = 0; i < 2; i++)
                wmma::load_matrix_sync(af[i], as + (wm * 32 + i * 16) * A_PAD + ks, A_PAD);
            #pragma unroll
            for (int j = 0; j < 4; j++)
                wmma::load_matrix_sync(bf[j], bs + ks * B_PAD + wn * 64 + j * 16, B_PAD);
            #pragma unroll
            for (int i = 0; i < 2; i++)
                #pragma unroll
                for (int j = 0; j < 4; j++)
                    wmma::mma_sync(acc[i][j], af[i], bf[j], acc[i][j]);
        }
    }
    __syncthreads();                    // all k-loop reads done before smem reuse

    // epilogue in two 64x128 halves staged at stride 132
    #pragma unroll 1
    for (int half = 0; half < 2; half++) {
        if ((wm >> 1) == half) {
            int rbase = wm * 32 - half * 64;
            #pragma unroll
            for (int i = 0; i < 2; i++)
                #pragma unroll
                for (int j = 0; j < 4; j++)
                    wmma::store_matrix_sync(sm + (rbase + i * 16) * B_PAD + wn * 64 + j * 16,
                                            acc[i][j], B_PAD, wmma::mem_row_major);
        }
        __syncthreads();
        // 64*128/4 = 2048 float4, 8 per thread
        for (int e = tid; e < 2048; e += 256) {
            int r = e >> 5;
            int c = (e & 31) << 2;
            float4 val = *(float4*)(sm + r * B_PAD + c);
            int gn = n0 + c;
            float4 bb = *(const float4*)(bias + gn);
            val.x += bb.x; val.y += bb.y; val.z += bb.z; val.w += bb.w;
            int gm = m0 + half * 64 + r;
            if (mode == 0) {
                val.x *= alpha; val.y *= alpha; val.z *= alpha; val.w *= alpha;
                *(float4*)(C + (size_t)gm * N + gn) = val;
            } else if (mode == 1) {
                val.x = fmaxf(val.x, 0.f); val.y = fmaxf(val.y, 0.f);
                val.z = fmaxf(val.z, 0.f); val.w = fmaxf(val.w, 0.f);
                *(float4*)(C + (size_t)gm * N + gn) = val;
            } else if (mode == 2) {
                float4 cv = *(float4*)(C + (size_t)gm * N + gn);
                val.x += cv.x; val.y += cv.y; val.z += cv.z; val.w += cv.w;
                *(float4*)(C + (size_t)gm * N + gn) = val;
            } else {
                size_t off = (size_t)winrev_row(gm) * N + gn;
                float4 rv = *(const float4*)(res + off);
                val.x += rv.x; val.y += rv.y; val.z += rv.z; val.w += rv.w;
                *(float4*)(C + off) = val;
            }
        }
        __syncthreads();
    }
}

// ---------------- attention: one block per (window, head) ----------------
// dynamic smem (49,664 B): qs 64x64 (reused for V), ktr stride-65, ps stride-65
#define PS_STRIDE 65
__global__ __launch_bounds__(256) void attn_kernel(
    const float* __restrict__ q, const float* __restrict__ k,
    const float* __restrict__ v, const float* __restrict__ vs, const float* __restrict__ vh,
    const float* __restrict__ rpb,
    float* __restrict__ o, float* __restrict__ os, float* __restrict__ oh)
{
    extern __shared__ float dsm[];
    float* qs  = dsm;                 // 64*64 = 4096
    float* ktr = dsm + 4096;          // 64*65 = 4160, kt[d*65 + m]
    float* ps  = dsm + 4096 + 4160;   // 64*65 = 4160, ps[n*65 + m]

    int win = blockIdx.x;
    int head = blockIdx.y;
    int tid = threadIdx.x;
    size_t base = (size_t)win * 64 * EDIM + head * 64;

    for (int f4 = tid; f4 < 1024; f4 += 256) {
        int n = f4 >> 4;
        int c = (f4 & 15) << 2;
        float4 qv = *(const float4*)(q + base + (size_t)n * EDIM + c);
        *(float4*)(qs + n * 64 + c) = qv;
        float4 kv = *(const float4*)(k + base + (size_t)n * EDIM + c);
        ktr[(c + 0) * 65 + n] = kv.x;
        ktr[(c + 1) * 65 + n] = kv.y;
        ktr[(c + 2) * 65 + n] = kv.z;
        ktr[(c + 3) * 65 + n] = kv.w;
    }
    __syncthreads();

    int n0 = (tid >> 4) << 2;
    int m0 = (tid & 15) << 2;

    float acc[4][4];
    #pragma unroll
    for (int i = 0; i < 4; i++)
        #pragma unroll
        for (int j = 0; j < 4; j++) acc[i][j] = 0.f;

    #pragma unroll 4
    for (int d = 0; d < 64; d++) {
        float qr[4], kr[4];
        #pragma unroll
        for (int i = 0; i < 4; i++) qr[i] = qs[(n0 + i) * 64 + d];
        #pragma unroll
        for (int j = 0; j < 4; j++) kr[j] = ktr[d * 65 + m0 + j];
        #pragma unroll
        for (int i = 0; i < 4; i++)
            #pragma unroll
            for (int j = 0; j < 4; j++)
                acc[i][j] = fmaf(qr[i], kr[j], acc[i][j]);
    }

    // rel-pos bias + shifted-window mask (window coordinates, unrolled mask grid)
    int wi = win & 63;
    int wh = wi >> 3, ww = wi & 7;
    #pragma unroll
    for (int i = 0; i < 4; i++) {
        int nn = n0 + i;
        int ni = nn >> 3, nj = nn & 7;
        int yn = wh * 8 + ni, xn = ww * 8 + nj;
        int idn = ((yn < 56) ? 0 : (yn < 60) ? 1 : 2) * 3 +
                  ((xn < 56) ? 0 : (xn < 60) ? 1 : 2);
        #pragma unroll
        for (int j = 0; j < 4; j++) {
            int mm = m0 + j;
            int mi = mm >> 3, mj = mm & 7;
            float rb = rpb[(((ni - mi + 7) * 15) + (nj - mj + 7)) * 8 + head];
            int ym = wh * 8 + mi, xm = ww * 8 + mj;
            int idm = ((ym < 56) ? 0 : (ym < 60) ? 1 : 2) * 3 +
                      ((xm < 56) ? 0 : (xm < 60) ? 1 : 2);
            float msk = (idn == idm) ? 0.f : -100.f;
            ps[nn * PS_STRIDE + mm] = acc[i][j] + rb + msk;
        }
    }
    __syncthreads();

    // softmax: one thread per row (stride-65 -> conflict-free)
    if (tid < 64) {
        float mx = -1e30f;
        for (int m = 0; m < 64; m++) mx = fmaxf(mx, ps[tid * PS_STRIDE + m]);
        float sum = 0.f;
        for (int m = 0; m < 64; m++) {
            float e = __expf(ps[tid * PS_STRIDE + m] - mx);
            ps[tid * PS_STRIDE + m] = e;
            sum += e;
        }
        float inv = 1.f / sum;
        for (int m = 0; m < 64; m++) ps[tid * PS_STRIDE + m] *= inv;
    }

    const float* vptr[3] = {v, vs, vh};
    float* optr[3] = {o, os, oh};
    #pragma unroll 1
    for (int t3 = 0; t3 < 3; t3++) {
        __syncthreads();                                  // qs free to reuse
        const float* vp = vptr[t3];
        for (int f4 = tid; f4 < 1024; f4 += 256) {
            int n = f4 >> 4;
            int c = (f4 & 15) << 2;
            *(float4*)(qs + n * 64 + c) = *(const float4*)(vp + base + (size_t)n * EDIM + c);
        }
        __syncthreads();
        float oa[4][4];
        #pragma unroll
        for (int i = 0; i < 4; i++)
            #pragma unroll
            for (int j = 0; j < 4; j++) oa[i][j] = 0.f;
        #pragma unroll 4
        for (int m = 0; m < 64; m++) {
            float pr[4];
            #pragma unroll
            for (int i = 0; i < 4; i++) pr[i] = ps[(n0 + i) * PS_STRIDE + m];
            float4 vv = *(const float4*)(qs + m * 64 + m0);
            #pragma unroll
            for (int i = 0; i < 4; i++) {
                oa[i][0] = fmaf(pr[i], vv.x, oa[i][0]);
                oa[i][1] = fmaf(pr[i], vv.y, oa[i][1]);
                oa[i][2] = fmaf(pr[i], vv.z, oa[i][2]);
                oa[i][3] = fmaf(pr[i], vv.w, oa[i][3]);
            }
        }
        float* op = optr[t3];
        #pragma unroll
        for (int i = 0; i < 4; i++) {
            float4 w4 = make_float4(oa[i][0], oa[i][1], oa[i][2], oa[i][3]);
            *(float4*)(op + base + (size_t)(n0 + i) * EDIM + m0) = w4;
        }
    }
}

#define ATTN_SMEM ((4096 + 4160 + 4160) * 4)

// ---------------- host launcher ----------------
extern "C" void kernel_launch(void* const* d_in, const int* in_sizes, int n_in,
                              void* d_out, int out_size)
{
    (void)in_sizes; (void)n_in; (void)out_size;

    const float* x    = (const float*)d_in[0];
    const float* scl  = (const float*)d_in[1];
    const float* sft  = (const float*)d_in[2];
    const float* wq   = (const float*)d_in[3];
    const float* bq   = (const float*)d_in[4];
    const float* wk   = (const float*)d_in[5];
    const float* bk   = (const float*)d_in[6];
    const float* wv   = (const float*)d_in[7];
    const float* bv   = (const float*)d_in[8];
    const float* wvs  = (const float*)d_in[9];
    const float* bvs  = (const float*)d_in[10];
    const float* wvh  = (const float*)d_in[11];
    const float* bvh  = (const float*)d_in[12];
    const float* wpx  = (const float*)d_in[13];
    const float* bpx  = (const float*)d_in[14];
    const float* wps  = (const float*)d_in[15];
    const float* bps  = (const float*)d_in[16];
    const float* wph  = (const float*)d_in[17];
    const float* bph  = (const float*)d_in[18];
    const float* rpb  = (const float*)d_in[19];
    const float* w1x  = (const float*)d_in[20];
    const float* b1x  = (const float*)d_in[21];
    const float* w2x  = (const float*)d_in[22];
    const float* b2x  = (const float*)d_in[23];
    const float* w1s  = (const float*)d_in[24];
    const float* b1s  = (const float*)d_in[25];
    const float* w2s  = (const float*)d_in[26];
    const float* b2s  = (const float*)d_in[27];
    const float* w1h  = (const float*)d_in[28];
    const float* b1h  = (const float*)d_in[29];
    const float* w2h  = (const float*)d_in[30];
    const float* b2h  = (const float*)d_in[31];

    float *p_xw, *p_sw, *p_hw, *p_q, *p_k, *p_v, *p_vs, *p_vh, *p_o, *p_os, *p_oh, *p_hid;
    cudaGetSymbolAddress((void**)&p_xw, g_xw);
    cudaGetSymbolAddress((void**)&p_sw, g_sw);
    cudaGetSymbolAddress((void**)&p_hw, g_hw);
    cudaGetSymbolAddress((void**)&p_q,  g_q);
    cudaGetSymbolAddress((void**)&p_k,  g_k);
    cudaGetSymbolAddress((void**)&p_v,  g_v);
    cudaGetSymbolAddress((void**)&p_vs, g_vs);
    cudaGetSymbolAddress((void**)&p_vh, g_vh);
    cudaGetSymbolAddress((void**)&p_o,  g_o);
    cudaGetSymbolAddress((void**)&p_os, g_os);
    cudaGetSymbolAddress((void**)&p_oh, g_oh);
    cudaGetSymbolAddress((void**)&p_hid, g_hid);

    float* outx = (float*)d_out;
    float* outs = outx + (size_t)TD;
    float* outh = outx + (size_t)2 * TD;

    cudaFuncSetAttribute(attn_kernel, cudaFuncAttributeMaxDynamicSharedMemorySize, ATTN_SMEM);
    cudaFuncSetAttribute(gemm_tf32_v6, cudaFuncAttributeMaxDynamicSharedMemorySize, GEMM_SMEM);

    dim3 blk(256);
    dim3 g512(EDIM / BN, NTOK / BM);    // (4, 512)
    dim3 g2048(EHID / BN, NTOK / BM);   // (16, 512)

    // 1. shift + window partition for x / scale / shift
    gather3<<<NTOK, 128>>>(x, scl, sft, p_xw, p_sw, p_hw);

    // 2. projections (q scaled by HD^-0.5 = 0.125)
    gemm_tf32_v6<<<g512, blk, GEMM_SMEM>>>(p_xw, wq,  bq,  p_q,  nullptr, NTOK, EDIM, EDIM, 0, 0.125f);
    gemm_tf32_v6<<<g512, blk, GEMM_SMEM>>>(p_xw, wk,  bk,  p_k,  nullptr, NTOK, EDIM, EDIM, 0, 1.f);
    gemm_tf32_v6<<<g512, blk, GEMM_SMEM>>>(p_xw, wv,  bv,  p_v,  nullptr, NTOK, EDIM, EDIM, 0, 1.f);
    gemm_tf32_v6<<<g512, blk, GEMM_SMEM>>>(p_sw, wvs, bvs, p_vs, nullptr, NTOK, EDIM, EDIM, 0, 1.f);
    gemm_tf32_v6<<<g512, blk, GEMM_SMEM>>>(p_hw, wvh, bvh, p_vh, nullptr, NTOK, EDIM, EDIM, 0, 1.f);

    // 3. windowed attention (shared softmax, three V streams)
    attn_kernel<<<dim3(1024, 8), 256, ATTN_SMEM>>>(p_q, p_k, p_v, p_vs, p_vh, rpb, p_o, p_os, p_oh);

    // 4. output projections + window reverse + residual (scatter into d_out)
    gemm_tf32_v6<<<g512, blk, GEMM_SMEM>>>(p_o,  wpx, bpx, outx, x,   NTOK, EDIM, EDIM, 3, 1.f);
    gemm_tf32_v6<<<g512, blk, GEMM_SMEM>>>(p_os, wps, bps, outs, scl, NTOK, EDIM, EDIM, 3, 1.f);
    gemm_tf32_v6<<<g512, blk, GEMM_SMEM>>>(p_oh, wph, bph, outh, sft, NTOK, EDIM, EDIM, 3, 1.f);

    // 5. MLPs with residual accumulate
    gemm_tf32_v6<<<g2048, blk, GEMM_SMEM>>>(outx,  w1x, b1x, p_hid, nullptr, NTOK, EHID, EDIM, 1, 1.f);
    gemm_tf32_v6<<<g512,  blk, GEMM_SMEM>>>(p_hid, w2x, b2x, outx,  nullptr, NTOK, EDIM, EHID, 2, 1.f);

    gemm_tf32_v6<<<g2048, blk, GEMM_SMEM>>>(outs,  w1s, b1s, p_hid, nullptr, NTOK, EHID, EDIM, 1, 1.f);
    gemm_tf32_v6<<<g512,  blk, GEMM_SMEM>>>(p_hid, w2s, b2s, outs,  nullptr, NTOK, EDIM, EHID, 2, 1.f);

    gemm_tf32_v6<<<g2048, blk, GEMM_SMEM>>>(outh,  w1h, b1h, p_hid, nullptr, NTOK, EHID, EDIM, 1, 1.f);
    gemm_tf32_v6<<<g512,  blk, GEMM_SMEM>>>(p_hid, w2h, b2h, outh,  nullptr, NTOK, EDIM, EHID, 2, 1.f);
}

// round 17
// speedup vs baseline: 5.1916x; 3.0823x over previous
#include <cuda_runtime.h>
#include <cuda_pipeline.h>
#include <cuda_fp16.h>
#include <mma.h>

using namespace nvcuda;

#define NTOK 65536          // B * H * W = 16 * 64 * 64
#define EDIM 512
#define EHID 2048
#define TD (NTOK * EDIM)    // elements per (token, dim) tensor

// ---------------- scratch (static device globals; no allocations) ----------------
__device__ __half g_xwh[TD];            // windowed inputs (half)
__device__ __half g_swh[TD];
__device__ __half g_hwh[TD];
__device__ float  g_q[TD];              // attention operands (float)
__device__ float  g_k[TD];
__device__ float  g_v[TD];
__device__ float  g_vs[TD];
__device__ float  g_vh[TD];
__device__ __half g_ox[TD];             // attention outputs (half)
__device__ __half g_os[TD];
__device__ __half g_oh2[TD];
__device__ __half g_pxh[TD];            // post-proj activations (half, original order)
__device__ __half g_psh[TD];
__device__ __half g_phh[TD];
__device__ __half g_hidh[NTOK * EHID];  // MLP hidden (half)
__device__ __half g_wh[8388608];        // all weights converted to half (16 MB)

// half-weight offsets (same [K][N] row-major layout as inputs)
#define WH_Q   0
#define WH_K   262144
#define WH_V   524288
#define WH_VS  786432
#define WH_VH  1048576
#define WH_PX  1310720
#define WH_PS  1572864
#define WH_PH  1835008
#define WH_1X  2097152
#define WH_1S  3145728
#define WH_1H  4194304
#define WH_2X  5242880
#define WH_2S  6291456
#define WH_2H  7340032

// windowed token t -> original token (also the window-reverse scatter target)
__device__ __forceinline__ int winrev_row(int t) {
    int b   = t >> 12;
    int win = (t >> 6) & 63;
    int n   = t & 63;
    int oh  = (((win >> 3) << 3) + (n >> 3) + 4) & 63;
    int ow  = (((win & 7) << 3) + (n & 7) + 4) & 63;
    return (b << 12) + (oh << 6) + ow;
}

// ---------------- weight fp32 -> fp16 convert ----------------
__global__ __launch_bounds__(256) void convert_w(
    const float* __restrict__ W, __half* __restrict__ WH, int n)
{
    int i = (blockIdx.x * 256 + threadIdx.x) * 4;
    if (i < n) {
        float4 v = *(const float4*)(W + i);
        *(__half2*)(WH + i)     = __floats2half2_rn(v.x, v.y);
        *(__half2*)(WH + i + 2) = __floats2half2_rn(v.z, v.w);
    }
}

// ---------------- gather: cyclic shift (-4,-4) + window partition -> half ----------
__global__ __launch_bounds__(128) void gather3(
    const float* __restrict__ x, const float* __restrict__ s, const float* __restrict__ h,
    __half* __restrict__ xw, __half* __restrict__ sw, __half* __restrict__ hw)
{
    int t = blockIdx.x;
    int c = threadIdx.x << 2;
    size_t src = (size_t)winrev_row(t) * EDIM + c;
    size_t dst = (size_t)t * EDIM + c;
    float4 a = *(const float4*)(x + src);
    *(__half2*)(xw + dst)     = __floats2half2_rn(a.x, a.y);
    *(__half2*)(xw + dst + 2) = __floats2half2_rn(a.z, a.w);
    float4 b = *(const float4*)(s + src);
    *(__half2*)(sw + dst)     = __floats2half2_rn(b.x, b.y);
    *(__half2*)(sw + dst + 2) = __floats2half2_rn(b.z, b.w);
    float4 d = *(const float4*)(h + src);
    *(__half2*)(hw + dst)     = __floats2half2_rn(d.x, d.y);
    *(__half2*)(hw + dst + 2) = __floats2half2_rn(d.z, d.w);
}

// ---------------- fp16 wmma GEMM: 128x128x32 tile, 2-stage cp.async -------------
// A: M x K row-major half. B: K x N row-major half. fp32 accumulate.
// mode 0: C(float) = alpha * val                       (QKV -> attention)
// mode 1: Ch(half) = relu(val)                         (MLP1 -> hidden)
// mode 2: C(float) += val                              (MLP2 residual accumulate)
// mode 3: C[map] = res[map] + val; Ch[map] = same      (proj + winrev + residual)
#define BM 128
#define BN 128
#define BK 32
#define A_PAD 40                        // halfs (80 B rows: conflict-free LDSM)
#define B_PAD 136                       // halfs (272 B rows)
#define A_STAGE (BM * A_PAD)            // 5120 halfs
#define B_STAGE (BK * B_PAD)            // 4352 halfs
#define GEMM_SMEM (2 * (A_STAGE + B_STAGE) * 2)     // 37,888 bytes (>= 33,792 epi)

__global__ __launch_bounds__(256, 2) void gemm_fp16(
    const __half* __restrict__ A, const __half* __restrict__ Bm,
    const float* __restrict__ bias, float* __restrict__ C, __half* __restrict__ Ch,
    const float* __restrict__ res,
    int M, int N, int K, int mode, float alpha)
{
    extern __shared__ char smc[];
    __half* As = (__half*)smc;                  // 2 stages of 128x40
    __half* Bs = As + 2 * A_STAGE;              // 2 stages of 32x136
    float* epi = (float*)smc;                   // epilogue staging overlay

    int tid = threadIdx.x;
    int warp = tid >> 5;
    int wm = warp >> 1;                 // 0..3: 32-row band
    int wn = warp & 1;                  // 0..1: 64-col band
    int m0 = blockIdx.y * BM;
    int n0 = blockIdx.x * BN;

    wmma::fragment<wmma::accumulator, 16, 16, 16, float> acc[2][4];
    #pragma unroll
    for (int i = 0; i < 2; i++)
        #pragma unroll
        for (int j = 0; j < 4; j++) wmma::fill_fragment(acc[i][j], 0.0f);

    // tile loader: A 512 chunks (2/thread), B 512 chunks (2/thread); 16B each
    auto load_tile = [&](int s, int ko) {
        __half* as = As + s * A_STAGE;
        __half* bs = Bs + s * B_STAGE;
        #pragma unroll
        for (int i = 0; i < 2; i++) {
            int id = tid * 2 + i;
            int r = id >> 2, c = (id & 3) << 3;         // 4 chunks per 32-half row
            __pipeline_memcpy_async(as + r * A_PAD + c,
                                    A + (size_t)(m0 + r) * K + ko + c, 16);
        }
        #pragma unroll
        for (int i = 0; i < 2; i++) {
            int id = tid * 2 + i;
            int r = id >> 4, c = (id & 15) << 3;        // 16 chunks per 128-half row
            __pipeline_memcpy_async(bs + r * B_PAD + c,
                                    Bm + (size_t)(ko + r) * N + n0 + c, 16);
        }
    };

    int ktiles = K / BK;                // 16 (K=512) or 64 (K=2048)
    load_tile(0, 0);
    __pipeline_commit();

    for (int kt = 0; kt < ktiles; kt++) {
        __pipeline_wait_prior(0);
        __syncthreads();
        if (kt + 1 < ktiles) {
            load_tile((kt + 1) & 1, (kt + 1) * BK);
            __pipeline_commit();
        }

        __half* as = As + (kt & 1) * A_STAGE;
        __half* bs = Bs + (kt & 1) * B_STAGE;
        #pragma unroll
        for (int ks = 0; ks < BK; ks += 16) {
            wmma::fragment<wmma::matrix_a, 16, 16, 16, __half, wmma::row_major> af[2];
            wmma::fragment<wmma::matrix_b, 16, 16, 16, __half, wmma::row_major> bf[4];
            #pragma unroll
            for (int i = 0; i < 2; i++)
                wmma::load_matrix_sync(af[i], as + (wm * 32 + i * 16) * A_PAD + ks, A_PAD);
            #pragma unroll
            for (int j = 0; j < 4; j++)
                wmma::load_matrix_sync(bf[j], bs + ks * B_PAD + wn * 64 + j * 16, B_PAD);
            #pragma unroll
            for (int i = 0; i < 2; i++)
                #pragma unroll
                for (int j = 0; j < 4; j++)
                    wmma::mma_sync(acc[i][j], af[i], bf[j], acc[i][j]);
        }
    }
    __syncthreads();

    // epilogue in two 64x128 halves staged at float stride 132
    #pragma unroll 1
    for (int half_ = 0; half_ < 2; half_++) {
        if ((wm >> 1) == half_) {
            int rbase = wm * 32 - half_ * 64;
            #pragma unroll
            for (int i = 0; i < 2; i++)
                #pragma unroll
                for (int j = 0; j < 4; j++)
                    wmma::store_matrix_sync(epi + (rbase + i * 16) * 132 + wn * 64 + j * 16,
                                            acc[i][j], 132, wmma::mem_row_major);
        }
        __syncthreads();
        for (int e = tid; e < 2048; e += 256) {
            int r = e >> 5;
            int c = (e & 31) << 2;
            float4 val = *(float4*)(epi + r * 132 + c);
            int gn = n0 + c;
            float4 bb = *(const float4*)(bias + gn);
            val.x += bb.x; val.y += bb.y; val.z += bb.z; val.w += bb.w;
            int gm = m0 + half_ * 64 + r;
            if (mode == 0) {
                val.x *= alpha; val.y *= alpha; val.z *= alpha; val.w *= alpha;
                *(float4*)(C + (size_t)gm * N + gn) = val;
            } else if (mode == 1) {
                val.x = fmaxf(val.x, 0.f); val.y = fmaxf(val.y, 0.f);
                val.z = fmaxf(val.z, 0.f); val.w = fmaxf(val.w, 0.f);
                size_t idx = (size_t)gm * N + gn;
                *(__half2*)(Ch + idx)     = __floats2half2_rn(val.x, val.y);
                *(__half2*)(Ch + idx + 2) = __floats2half2_rn(val.z, val.w);
            } else if (mode == 2) {
                float4 cv = *(float4*)(C + (size_t)gm * N + gn);
                val.x += cv.x; val.y += cv.y; val.z += cv.z; val.w += cv.w;
                *(float4*)(C + (size_t)gm * N + gn) = val;
            } else {
                size_t off = (size_t)winrev_row(gm) * N + gn;
                float4 rv = *(const float4*)(res + off);
                val.x += rv.x; val.y += rv.y; val.z += rv.z; val.w += rv.w;
                *(float4*)(C + off) = val;
                *(__half2*)(Ch + off)     = __floats2half2_rn(val.x, val.y);
                *(__half2*)(Ch + off + 2) = __floats2half2_rn(val.z, val.w);
            }
        }
        __syncthreads();
    }
}

// ---------------- attention: one block per (window, head); half outputs ----------
#define PS_STRIDE 65
__global__ __launch_bounds__(256) void attn_kernel(
    const float* __restrict__ q, const float* __restrict__ k,
    const float* __restrict__ v, const float* __restrict__ vs, const float* __restrict__ vh,
    const float* __restrict__ rpb,
    __half* __restrict__ o, __half* __restrict__ os, __half* __restrict__ oh)
{
    extern __shared__ float dsm[];
    float* qs  = dsm;                 // 64*64 = 4096
    float* ktr = dsm + 4096;          // 64*65
    float* ps  = dsm + 4096 + 4160;   // 64*65

    int win = blockIdx.x;
    int head = blockIdx.y;
    int tid = threadIdx.x;
    size_t base = (size_t)win * 64 * EDIM + head * 64;

    for (int f4 = tid; f4 < 1024; f4 += 256) {
        int n = f4 >> 4;
        int c = (f4 & 15) << 2;
        float4 qv = *(const float4*)(q + base + (size_t)n * EDIM + c);
        *(float4*)(qs + n * 64 + c) = qv;
        float4 kv = *(const float4*)(k + base + (size_t)n * EDIM + c);
        ktr[(c + 0) * 65 + n] = kv.x;
        ktr[(c + 1) * 65 + n] = kv.y;
        ktr[(c + 2) * 65 + n] = kv.z;
        ktr[(c + 3) * 65 + n] = kv.w;
    }
    __syncthreads();

    int n0 = (tid >> 4) << 2;
    int m0 = (tid & 15) << 2;

    float acc[4][4];
    #pragma unroll
    for (int i = 0; i < 4; i++)
        #pragma unroll
        for (int j = 0; j < 4; j++) acc[i][j] = 0.f;

    #pragma unroll 4
    for (int d = 0; d < 64; d++) {
        float qr[4], kr[4];
        #pragma unroll
        for (int i = 0; i < 4; i++) qr[i] = qs[(n0 + i) * 64 + d];
        #pragma unroll
        for (int j = 0; j < 4; j++) kr[j] = ktr[d * 65 + m0 + j];
        #pragma unroll
        for (int i = 0; i < 4; i++)
            #pragma unroll
            for (int j = 0; j < 4; j++)
                acc[i][j] = fmaf(qr[i], kr[j], acc[i][j]);
    }

    int wi = win & 63;
    int wh = wi >> 3, ww = wi & 7;
    #pragma unroll
    for (int i = 0; i < 4; i++) {
        int nn = n0 + i;
        int ni = nn >> 3, nj = nn & 7;
        int yn = wh * 8 + ni, xn = ww * 8 + nj;
        int idn = ((yn < 56) ? 0 : (yn < 60) ? 1 : 2) * 3 +
                  ((xn < 56) ? 0 : (xn < 60) ? 1 : 2);
        #pragma unroll
        for (int j = 0; j < 4; j++) {
            int mm = m0 + j;
            int mi = mm >> 3, mj = mm & 7;
            float rb = rpb[(((ni - mi + 7) * 15) + (nj - mj + 7)) * 8 + head];
            int ym = wh * 8 + mi, xm = ww * 8 + mj;
            int idm = ((ym < 56) ? 0 : (ym < 60) ? 1 : 2) * 3 +
                      ((xm < 56) ? 0 : (xm < 60) ? 1 : 2);
            float msk = (idn == idm) ? 0.f : -100.f;
            ps[nn * PS_STRIDE + mm] = acc[i][j] + rb + msk;
        }
    }
    __syncthreads();

    if (tid < 64) {
        float mx = -1e30f;
        for (int m = 0; m < 64; m++) mx = fmaxf(mx, ps[tid * PS_STRIDE + m]);
        float sum = 0.f;
        for (int m = 0; m < 64; m++) {
            float e = __expf(ps[tid * PS_STRIDE + m] - mx);
            ps[tid * PS_STRIDE + m] = e;
            sum += e;
        }
        float inv = 1.f / sum;
        for (int m = 0; m < 64; m++) ps[tid * PS_STRIDE + m] *= inv;
    }

    const float* vptr[3] = {v, vs, vh};
    __half* optr[3] = {o, os, oh};
    #pragma unroll 1
    for (int t3 = 0; t3 < 3; t3++) {
        __syncthreads();
        const float* vp = vptr[t3];
        for (int f4 = tid; f4 < 1024; f4 += 256) {
            int n = f4 >> 4;
            int c = (f4 & 15) << 2;
            *(float4*)(qs + n * 64 + c) = *(const float4*)(vp + base + (size_t)n * EDIM + c);
        }
        __syncthreads();
        float oa[4][4];
        #pragma unroll
        for (int i = 0; i < 4; i++)
            #pragma unroll
            for (int j = 0; j < 4; j++) oa[i][j] = 0.f;
        #pragma unroll 4
        for (int m = 0; m < 64; m++) {
            float pr[4];
            #pragma unroll
            for (int i = 0; i < 4; i++) pr[i] = ps[(n0 + i) * PS_STRIDE + m];
            float4 vv = *(const float4*)(qs + m * 64 + m0);
            #pragma unroll
            for (int i = 0; i < 4; i++) {
                oa[i][0] = fmaf(pr[i], vv.x, oa[i][0]);
                oa[i][1] = fmaf(pr[i], vv.y, oa[i][1]);
                oa[i][2] = fmaf(pr[i], vv.z, oa[i][2]);
                oa[i][3] = fmaf(pr[i], vv.w, oa[i][3]);
            }
        }
        __half* op = optr[t3];
        #pragma unroll
        for (int i = 0; i < 4; i++) {
            size_t idx = base + (size_t)(n0 + i) * EDIM + m0;
            *(__half2*)(op + idx)     = __floats2half2_rn(oa[i][0], oa[i][1]);
            *(__half2*)(op + idx + 2) = __floats2half2_rn(oa[i][2], oa[i][3]);
        }
    }
}

#define ATTN_SMEM ((4096 + 4160 + 4160) * 4)

// ---------------- host launcher ----------------
extern "C" void kernel_launch(void* const* d_in, const int* in_sizes, int n_in,
                              void* d_out, int out_size)
{
    (void)in_sizes; (void)n_in; (void)out_size;

    const float* x    = (const float*)d_in[0];
    const float* scl  = (const float*)d_in[1];
    const float* sft  = (const float*)d_in[2];
    const float* wq   = (const float*)d_in[3];
    const float* bq   = (const float*)d_in[4];
    const float* wk   = (const float*)d_in[5];
    const float* bk   = (const float*)d_in[6];
    const float* wv   = (const float*)d_in[7];
    const float* bv   = (const float*)d_in[8];
    const float* wvs  = (const float*)d_in[9];
    const float* bvs  = (const float*)d_in[10];
    const float* wvh  = (const float*)d_in[11];
    const float* bvh  = (const float*)d_in[12];
    const float* wpx  = (const float*)d_in[13];
    const float* bpx  = (const float*)d_in[14];
    const float* wps  = (const float*)d_in[15];
    const float* bps  = (const float*)d_in[16];
    const float* wph  = (const float*)d_in[17];
    const float* bph  = (const float*)d_in[18];
    const float* rpb  = (const float*)d_in[19];
    const float* w1x  = (const float*)d_in[20];
    const float* b1x  = (const float*)d_in[21];
    const float* w2x  = (const float*)d_in[22];
    const float* b2x  = (const float*)d_in[23];
    const float* w1s  = (const float*)d_in[24];
    const float* b1s  = (const float*)d_in[25];
    const float* w2s  = (const float*)d_in[26];
    const float* b2s  = (const float*)d_in[27];
    const float* w1h  = (const float*)d_in[28];
    const float* b1h  = (const float*)d_in[29];
    const float* w2h  = (const float*)d_in[30];
    const float* b2h  = (const float*)d_in[31];

    __half *p_xwh, *p_swh, *p_hwh, *p_ox, *p_os, *p_oh2, *p_pxh, *p_psh, *p_phh, *p_hidh, *p_wh;
    float *p_q, *p_k, *p_v, *p_vs, *p_vh;
    cudaGetSymbolAddress((void**)&p_xwh, g_xwh);
    cudaGetSymbolAddress((void**)&p_swh, g_swh);
    cudaGetSymbolAddress((void**)&p_hwh, g_hwh);
    cudaGetSymbolAddress((void**)&p_q,   g_q);
    cudaGetSymbolAddress((void**)&p_k,   g_k);
    cudaGetSymbolAddress((void**)&p_v,   g_v);
    cudaGetSymbolAddress((void**)&p_vs,  g_vs);
    cudaGetSymbolAddress((void**)&p_vh,  g_vh);
    cudaGetSymbolAddress((void**)&p_ox,  g_ox);
    cudaGetSymbolAddress((void**)&p_os,  g_os);
    cudaGetSymbolAddress((void**)&p_oh2, g_oh2);
    cudaGetSymbolAddress((void**)&p_pxh, g_pxh);
    cudaGetSymbolAddress((void**)&p_psh, g_psh);
    cudaGetSymbolAddress((void**)&p_phh, g_phh);
    cudaGetSymbolAddress((void**)&p_hidh, g_hidh);
    cudaGetSymbolAddress((void**)&p_wh,  g_wh);

    float* outx = (float*)d_out;
    float* outs = outx + (size_t)TD;
    float* outh = outx + (size_t)2 * TD;

    cudaFuncSetAttribute(attn_kernel, cudaFuncAttributeMaxDynamicSharedMemorySize, ATTN_SMEM);
    cudaFuncSetAttribute(gemm_fp16, cudaFuncAttributeMaxDynamicSharedMemorySize, GEMM_SMEM);

    dim3 tb(256);

    // 0. convert all weights to half (layout unchanged)
    convert_w<<<256, 256>>>(wq,  p_wh + WH_Q,  262144);
    convert_w<<<256, 256>>>(wk,  p_wh + WH_K,  262144);
    convert_w<<<256, 256>>>(wv,  p_wh + WH_V,  262144);
    convert_w<<<256, 256>>>(wvs, p_wh + WH_VS, 262144);
    convert_w<<<256, 256>>>(wvh, p_wh + WH_VH, 262144);
    convert_w<<<256, 256>>>(wpx, p_wh + WH_PX, 262144);
    convert_w<<<256, 256>>>(wps, p_wh + WH_PS, 262144);
    convert_w<<<256, 256>>>(wph, p_wh + WH_PH, 262144);
    convert_w<<<1024, 256>>>(w1x, p_wh + WH_1X, 1048576);
    convert_w<<<1024, 256>>>(w1s, p_wh + WH_1S, 1048576);
    convert_w<<<1024, 256>>>(w1h, p_wh + WH_1H, 1048576);
    convert_w<<<1024, 256>>>(w2x, p_wh + WH_2X, 1048576);
    convert_w<<<1024, 256>>>(w2s, p_wh + WH_2S, 1048576);
    convert_w<<<1024, 256>>>(w2h, p_wh + WH_2H, 1048576);

    // 1. shift + window partition (half)
    gather3<<<NTOK, 128>>>(x, scl, sft, p_xwh, p_swh, p_hwh);

    dim3 g512(EDIM / BN, NTOK / BM);    // (4, 512)
    dim3 g2048(EHID / BN, NTOK / BM);   // (16, 512)

    // 2. projections (float out; q scaled by 0.125)
    gemm_fp16<<<g512, tb, GEMM_SMEM>>>(p_xwh, p_wh + WH_Q,  bq,  p_q,  nullptr, nullptr, NTOK, EDIM, EDIM, 0, 0.125f);
    gemm_fp16<<<g512, tb, GEMM_SMEM>>>(p_xwh, p_wh + WH_K,  bk,  p_k,  nullptr, nullptr, NTOK, EDIM, EDIM, 0, 1.f);
    gemm_fp16<<<g512, tb, GEMM_SMEM>>>(p_xwh, p_wh + WH_V,  bv,  p_v,  nullptr, nullptr, NTOK, EDIM, EDIM, 0, 1.f);
    gemm_fp16<<<g512, tb, GEMM_SMEM>>>(p_swh, p_wh + WH_VS, bvs, p_vs, nullptr, nullptr, NTOK, EDIM, EDIM, 0, 1.f);
    gemm_fp16<<<g512, tb, GEMM_SMEM>>>(p_hwh, p_wh + WH_VH, bvh, p_vh, nullptr, nullptr, NTOK, EDIM, EDIM, 0, 1.f);

    // 3. windowed attention (half outputs)
    attn_kernel<<<dim3(1024, 8), 256, ATTN_SMEM>>>(p_q, p_k, p_v, p_vs, p_vh, rpb, p_ox, p_os, p_oh2);

    // 4. output projections + winrev + residual (float scatter to d_out + half copy)
    gemm_fp16<<<g512, tb, GEMM_SMEM>>>(p_ox,  p_wh + WH_PX, bpx, outx, p_pxh, x,   NTOK, EDIM, EDIM, 3, 1.f);
    gemm_fp16<<<g512, tb, GEMM_SMEM>>>(p_os,  p_wh + WH_PS, bps, outs, p_psh, scl, NTOK, EDIM, EDIM, 3, 1.f);
    gemm_fp16<<<g512, tb, GEMM_SMEM>>>(p_oh2, p_wh + WH_PH, bph, outh, p_phh, sft, NTOK, EDIM, EDIM, 3, 1.f);

    // 5. MLPs: relu hidden (half), then residual accumulate (float)
    gemm_fp16<<<g2048, tb, GEMM_SMEM>>>(p_pxh, p_wh + WH_1X, b1x, nullptr, p_hidh, nullptr, NTOK, EHID, EDIM, 1, 1.f);
    gemm_fp16<<<g512,  tb, GEMM_SMEM>>>(p_hidh, p_wh + WH_2X, b2x, outx, nullptr, nullptr, NTOK, EDIM, EHID, 2, 1.f);

    gemm_fp16<<<g2048, tb, GEMM_SMEM>>>(p_psh, p_wh + WH_1S, b1s, nullptr, p_hidh, nullptr, NTOK, EHID, EDIM, 1, 1.f);
    gemm_fp16<<<g512,  tb, GEMM_SMEM>>>(p_hidh, p_wh + WH_2S, b2s, outs, nullptr, nullptr, NTOK, EDIM, EHID, 2, 1.f);

    gemm_fp16<<<g2048, tb, GEMM_SMEM>>>(p_phh, p_wh + WH_1H, b1h, nullptr, p_hidh, nullptr, NTOK, EHID, EDIM, 1, 1.f);
    gemm_fp16<<<g512,  tb, GEMM_SMEM>>>(p_hidh, p_wh + WH_2H, b2h, outh, nullptr, nullptr, NTOK, EDIM, EHID, 2, 1.f);
}